// round 9
// baseline (speedup 1.0000x reference)
#include <cuda_runtime.h>

// GRU: T=2048, B=64, IN=256, H=256, L=3
// Output = [seq (2048*64*256) floats][h_n (3*64*256) floats]
//
// R7 design:
//  - gemm_gx: unchanged SGEMM, NCHUNK=4 chunks, overlapped on low-pri stream.
//  - gru_scan: 128 CTAs = 16 unit-groups x 8 batch-group-PAIRS. Each CTA owns
//    16 units (48 gate rows, register-resident f32x2) and TWO independent
//    4-batch groups (A/B), processed alternately each timestep so group A's
//    inter-SM barrier+L2 latency hides under group B's compute.
//  - Split-reduce: lanes 0-7 reduce even-batch sums, 8-15 odd-batch; one
//    shfl-idx gather at the end (30 SHFL vs 48 per group-step).

#define T_STEPS  2048
#define B_SZ     64
#define H_SZ     256
#define G3       768
#define M_TOT    (T_STEPS * B_SZ)
#define NCHUNK   4
#define CHUNK_T  (T_STEPS / NCHUNK)       // 512
#define CHUNK_M  (CHUNK_T * B_SZ)         // 32768

typedef unsigned long long u64;

// ---------------- device scratch (no cudaMalloc allowed) -------------------
__device__ float g_gx[(size_t)M_TOT * G3];     // 402 MB input projections
__device__ float g_seq[(size_t)M_TOT * H_SZ];  // 134 MB inter-layer sequence

struct PaddedCtr { unsigned int v; unsigned int pad[31]; };   // 128B apart
__device__ PaddedCtr g_bar[3][16];                             // [layer][bgroup]

__global__ void reset_kernel() {
    int i = threadIdx.x;
    if (i < 48) g_bar[i / 16][i % 16].v = 0u;
}

// ---------------- packed fp32 helpers ---------------------------------------
__device__ __forceinline__ void ffma2(u64 &d, u64 a, u64 b) {
    asm("fma.rn.f32x2 %0, %1, %2, %0;" : "+l"(d) : "l"(a), "l"(b));
}
__device__ __forceinline__ u64 pack2(float lo, float hi) {
    u64 r; asm("mov.b64 %0, {%1, %2};" : "=l"(r) : "f"(lo), "f"(hi)); return r;
}
__device__ __forceinline__ float2 unpack2(u64 v) {
    float2 r; asm("mov.b64 {%0, %1}, %2;" : "=f"(r.x), "=f"(r.y) : "l"(v)); return r;
}
__device__ __forceinline__ float fsigmoid(float x) {
    float e; asm("ex2.approx.f32 %0, %1;" : "=f"(e) : "f"(-1.4426950408889634f * x));
    float r; asm("rcp.approx.f32 %0, %1;" : "=f"(r) : "f"(1.0f + e));
    return r;
}
__device__ __forceinline__ float ftanh(float x) {
    float y; asm("tanh.approx.f32 %0, %1;" : "=f"(y) : "f"(x)); return y;
}

// ---------------- Phase A: gx GEMM  (chunked) -------------------------------
__global__ __launch_bounds__(256) void gemm_gx(
    const float* __restrict__ A,
    const float* __restrict__ W,
    const float* __restrict__ bias,
    int m_base)
{
    __shared__ __align__(16) float As[32 * 132];
    __shared__ __align__(16) float Bs[32 * 64];

    const int tid = threadIdx.x;
    const int tx  = tid & 15;
    const int ty  = tid >> 4;
    const int m0  = m_base + blockIdx.x * 128;
    const int n0  = blockIdx.y * 64;

    float acc[8][4];
#pragma unroll
    for (int i = 0; i < 8; i++)
#pragma unroll
        for (int j = 0; j < 4; j++) acc[i][j] = 0.0f;

    for (int k0 = 0; k0 < 256; k0 += 32) {
#pragma unroll
        for (int i = 0; i < 4; i++) {
            int f = tid + 256 * i;
            int r = f >> 3, c4 = f & 7;
            float4 v = *(const float4*)(A + (size_t)(m0 + r) * 256 + k0 + c4 * 4);
            As[(c4 * 4 + 0) * 132 + r] = v.x;
            As[(c4 * 4 + 1) * 132 + r] = v.y;
            As[(c4 * 4 + 2) * 132 + r] = v.z;
            As[(c4 * 4 + 3) * 132 + r] = v.w;
        }
#pragma unroll
        for (int i = 0; i < 2; i++) {
            int f = tid + 256 * i;
            int r = f >> 3, c4 = f & 7;
            float4 v = *(const float4*)(W + (size_t)(n0 + r) * 256 + k0 + c4 * 4);
            Bs[(c4 * 4 + 0) * 64 + r] = v.x;
            Bs[(c4 * 4 + 1) * 64 + r] = v.y;
            Bs[(c4 * 4 + 2) * 64 + r] = v.z;
            Bs[(c4 * 4 + 3) * 64 + r] = v.w;
        }
        __syncthreads();

#pragma unroll
        for (int k = 0; k < 32; k++) {
            float a[8], b[4];
            *(float4*)&a[0] = *(const float4*)&As[k * 132 + ty * 8];
            *(float4*)&a[4] = *(const float4*)&As[k * 132 + ty * 8 + 4];
            *(float4*)&b[0] = *(const float4*)&Bs[k * 64 + tx * 4];
#pragma unroll
            for (int i = 0; i < 8; i++)
#pragma unroll
                for (int j = 0; j < 4; j++)
                    acc[i][j] = fmaf(a[i], b[j], acc[i][j]);
        }
        __syncthreads();
    }

    float4 bv = *(const float4*)(bias + n0 + tx * 4);
#pragma unroll
    for (int i = 0; i < 8; i++) {
        float4 o;
        o.x = acc[i][0] + bv.x;
        o.y = acc[i][1] + bv.y;
        o.z = acc[i][2] + bv.z;
        o.w = acc[i][3] + bv.w;
        *(float4*)(g_gx + (size_t)(m0 + ty * 8 + i) * G3 + n0 + tx * 4) = o;
    }
}

// ---------------- Phase B: dual-group pipelined scan -------------------------
// 128 CTAs: bgpair = bid&7, ug = bid>>3. CTA owns units ug*16..+16 and batch
// groups {2*bgpair, 2*bgpair+1} (4 batches each). Warp w: units u0=ug*16+2w.
// Lanes: ks = l&15, bh = l>>4 -> local batches {2bh, 2bh+1} of the group.
__global__ __launch_bounds__(256, 1) void gru_scan(
    const float* __restrict__ h0l,
    const float* __restrict__ Whh,
    const float* __restrict__ bhh,
    float* __restrict__ seqout,
    float* __restrict__ hn_out,
    int t0, int t1, int layer)
{
    __shared__ __align__(16) float hs[4][256];     // staged h for current group

    const int tid = threadIdx.x;
    const int w   = tid >> 5;
    const int l   = tid & 31;
    const int ks  = l & 15;
    const int bh  = l >> 4;
    const int bgpair = blockIdx.x & 7;
    const int ug     = blockIdx.x >> 3;
    const int u0     = ug * 16 + w * 2;

    int rows[6];
    rows[0] = u0;       rows[1] = u0 + 1;
    rows[2] = 256 + u0; rows[3] = 257 + u0;
    rows[4] = 512 + u0; rows[5] = 513 + u0;

    u64 wk[6][8];
#pragma unroll
    for (int r = 0; r < 6; r++)
#pragma unroll
        for (int kk = 0; kk < 4; kk++) {
            float4 v = *(const float4*)(Whh + (size_t)rows[r] * 256 + kk * 64 + ks * 4);
            wk[r][kk * 2 + 0] = pack2(v.x, v.y);
            wk[r][kk * 2 + 1] = pack2(v.z, v.w);
        }
    float bh6[6];
#pragma unroll
    for (int r = 0; r < 6; r++) bh6[r] = bhh[rows[r]];

    const int  j       = ks;
    const bool is_comb = (ks < 2);            // combine lanes per 16-half
    const bool hi8     = ((ks & 8) != 0);     // split-reduce role

    // Per-group constants
    const int  bgroup0 = bgpair * 2;          // group g -> bgroup0 + g
    // combine lane's batch for group g: gb = (bgroup0+g)*4 + 2*bh + j

    // gx prefetch for both groups at t0
    u64 gxv[2][3];
#pragma unroll
    for (int g = 0; g < 2; g++)
        if (is_comb) {
            const int gb = (bgroup0 + g) * 4 + 2 * bh + j;
            const float* gp = g_gx + ((size_t)t0 * B_SZ + gb) * G3;
            gxv[g][0] = *(const u64*)(gp + u0);
            gxv[g][1] = *(const u64*)(gp + 256 + u0);
            gxv[g][2] = *(const u64*)(gp + 512 + u0);
        }

    const int stage_lb  = tid >> 6;            // staging: local batch 0..3
    const int stage_off = (tid & 63) * 4;

    for (int t = t0; t < t1; t++) {
#pragma unroll
        for (int g = 0; g < 2; g++) {
            const int bgroup = bgroup0 + g;
            const int gb0    = bgroup * 4;
            unsigned int* ctr = &g_bar[layer][bgroup].v;

            // 1) all-warp poll: group step t needs 16 releases of step t-1
            if (t > 0) {
                const unsigned int target = (unsigned int)t * 16u;
                unsigned int v;
                do {
                    asm volatile("ld.acquire.gpu.global.u32 %0, [%1];"
                                 : "=r"(v) : "l"(ctr) : "memory");
                } while (v < target);
            }

            // 2) stage h_{t-1} for this group's 4 batches (4 KB)
            {
                const float* hsrc = (t == 0) ? h0l
                                  : (seqout + (size_t)(t - 1) * (B_SZ * H_SZ));
                *(float4*)&hs[stage_lb][stage_off] =
                    __ldcg((const float4*)(hsrc + (size_t)(gb0 + stage_lb) * 256
                                           + stage_off));
            }
            __syncthreads();

            float hold0 = 0.0f, hold1 = 0.0f;
            if (is_comb) {
                hold0 = hs[2 * bh + j][u0];
                hold1 = hs[2 * bh + j][u0 + 1];
            }

            // 3) FFMA2 over the two local batches
            const int lA = 2 * bh, lB = lA + 1;
            u64 acc[6][2];
#pragma unroll
            for (int r = 0; r < 6; r++) { acc[r][0] = 0ULL; acc[r][1] = 0ULL; }
#pragma unroll
            for (int kk = 0; kk < 4; kk++) {
                ulonglong2 hA = *(const ulonglong2*)&hs[lA][kk * 64 + ks * 4];
                ulonglong2 hB = *(const ulonglong2*)&hs[lB][kk * 64 + ks * 4];
#pragma unroll
                for (int r = 0; r < 6; r++) {
                    ffma2(acc[r][0], wk[r][kk * 2 + 0], hA.x);
                    ffma2(acc[r][0], wk[r][kk * 2 + 1], hA.y);
                    ffma2(acc[r][1], wk[r][kk * 2 + 0], hB.x);
                    ffma2(acc[r][1], wk[r][kk * 2 + 1], hB.y);
                }
            }

            // 4) split reduce: low 8 lanes own batch-A sums, high 8 own B.
            float keep[6];
#pragma unroll
            for (int r = 0; r < 6; r++) {
                float2 a = unpack2(acc[r][0]);
                float2 b = unpack2(acc[r][1]);
                float sA = a.x + a.y, sB = b.x + b.y;
                float send = hi8 ? sA : sB;
                float recv = __shfl_xor_sync(0xFFFFFFFFu, send, 8);
                keep[r] = (hi8 ? sB : sA) + recv;
            }
#pragma unroll
            for (int off = 1; off < 8; off <<= 1) {
#pragma unroll
                for (int r = 0; r < 6; r++)
                    keep[r] += __shfl_xor_sync(0xFFFFFFFFu, keep[r], off);
            }
            // gather B-totals (live in lanes 8-15) down for combine lane 1
            float fetched[6];
#pragma unroll
            for (int r = 0; r < 6; r++)
                fetched[r] = __shfl_sync(0xFFFFFFFFu, keep[r], (l & 15) | 8, 16);

            // 5) combine: lane j=0 -> batch lA (keep), lane j=1 -> batch lB
            if (is_comb) {
                float s0, s1, s2, s3, s4, s5;
                if (j == 0) { s0=keep[0]; s1=keep[1]; s2=keep[2];
                              s3=keep[3]; s4=keep[4]; s5=keep[5]; }
                else        { s0=fetched[0]; s1=fetched[1]; s2=fetched[2];
                              s3=fetched[3]; s4=fetched[4]; s5=fetched[5]; }

                float2 gxr = unpack2(gxv[g][0]);
                float2 gxz = unpack2(gxv[g][1]);
                float2 gxn = unpack2(gxv[g][2]);

                float r0 = fsigmoid(gxr.x + s0 + bh6[0]);
                float z0 = fsigmoid(gxz.x + s2 + bh6[2]);
                float n0 = ftanh(gxn.x + r0 * (s4 + bh6[4]));
                float out0 = (1.0f - z0) * n0 + z0 * hold0;

                float r1 = fsigmoid(gxr.y + s1 + bh6[1]);
                float z1 = fsigmoid(gxz.y + s3 + bh6[3]);
                float n1 = ftanh(gxn.y + r1 * (s5 + bh6[5]));
                float out1 = (1.0f - z1) * n1 + z1 * hold1;

                const int gb = gb0 + 2 * bh + j;
                u64 o = pack2(out0, out1);
                *(u64*)&seqout[((size_t)t * B_SZ + gb) * H_SZ + u0] = o;
                if (t == T_STEPS - 1)
                    *(u64*)&hn_out[gb * 256 + u0] = o;

                // prefetch gx for t+1 (off the critical path)
                if (t + 1 < t1) {
                    const float* gp = g_gx + ((size_t)(t + 1) * B_SZ + gb) * G3;
                    gxv[g][0] = *(const u64*)(gp + u0);
                    gxv[g][1] = *(const u64*)(gp + 256 + u0);
                    gxv[g][2] = *(const u64*)(gp + 512 + u0);
                }
            }

            // 6) release this CTA's contribution to group g, step t
            __syncthreads();
            if (tid == 0)
                asm volatile("red.release.gpu.global.add.u32 [%0], 1;"
                             :: "l"(ctr) : "memory");
        }
    }
}

// ---------------- launch: pipelined DAG --------------------------------------
extern "C" void kernel_launch(void* const* d_in, const int* in_sizes, int n_in,
                              void* d_out, int out_size)
{
    const float* x   = (const float*)d_in[0];
    const float* h0  = (const float*)d_in[1];
    const float* Wih = (const float*)d_in[2];
    const float* Whh = (const float*)d_in[3];
    const float* bih = (const float*)d_in[4];
    const float* bhh = (const float*)d_in[5];

    float* out     = (float*)d_out;
    float* hn_base = out + (size_t)T_STEPS * B_SZ * H_SZ;

    void* gseq_ptr = nullptr;
    cudaGetSymbolAddress(&gseq_ptr, g_seq);
    float* gseq = (float*)gseq_ptr;

    static cudaStream_t s1 = nullptr;
    static cudaEvent_t evFork;
    static cudaEvent_t evG[3][NCHUNK];
    static cudaEvent_t evS[3][NCHUNK];
    if (!s1) {
        int loPri = 0, hiPri = 0;
        cudaDeviceGetStreamPriorityRange(&loPri, &hiPri);
        cudaStreamCreateWithPriority(&s1, cudaStreamNonBlocking, loPri);
        cudaEventCreateWithFlags(&evFork, cudaEventDisableTiming);
        for (int l = 0; l < 3; l++)
            for (int c = 0; c < NCHUNK; c++) {
                cudaEventCreateWithFlags(&evG[l][c], cudaEventDisableTiming);
                cudaEventCreateWithFlags(&evS[l][c], cudaEventDisableTiming);
            }
    }

    const size_t WSTRIDE = (size_t)G3 * 256;
    const size_t HSTRIDE = (size_t)B_SZ * H_SZ;
    const dim3 ggrid(CHUNK_M / 128, G3 / 64);   // (256, 12)

    reset_kernel<<<1, 64>>>();
    cudaEventRecord(evFork, 0);
    cudaStreamWaitEvent(s1, evFork, 0);

    // ---- layer 0: submit gemm c=0,1 first so ncu -s 5 lands on a scan ----
    {
        const float* h0l = h0;
        float* hn = hn_base;
        gemm_gx<<<ggrid, 256, 0, s1>>>(x, Wih, bih, 0 * CHUNK_M);
        cudaEventRecord(evG[0][0], s1);
        gemm_gx<<<ggrid, 256, 0, s1>>>(x, Wih, bih, 1 * CHUNK_M);
        cudaEventRecord(evG[0][1], s1);

        for (int c = 0; c < NCHUNK; c++) {
            if (c >= 2) {
                gemm_gx<<<ggrid, 256, 0, s1>>>(x, Wih, bih, c * CHUNK_M);
                cudaEventRecord(evG[0][c], s1);
            }
            // interleave: scan c-? — launch scan for chunk index (c<2 ? c : c)
            cudaStreamWaitEvent(0, evG[0][c], 0);
            gru_scan<<<128, 256>>>(h0l, Whh, bhh, gseq, hn,
                                   c * CHUNK_T, (c + 1) * CHUNK_T, 0);
            cudaEventRecord(evS[0][c], 0);
        }
    }

    // ---- layers 1, 2 ----
    for (int lyr = 1; lyr < 3; lyr++) {
        const float* A   = gseq;
        float*       so  = (lyr == 2) ? out : gseq;
        const float* wih = Wih + lyr * WSTRIDE;
        const float* whh = Whh + lyr * WSTRIDE;
        const float* bi  = bih + lyr * G3;
        const float* bh  = bhh + lyr * G3;
        const float* h0l = h0 + lyr * HSTRIDE;
        float*       hn  = hn_base + lyr * HSTRIDE;

        for (int c = 0; c < NCHUNK; c++) {
            cudaStreamWaitEvent(s1, evS[lyr - 1][c], 0);
            gemm_gx<<<ggrid, 256, 0, s1>>>(A, wih, bi, c * CHUNK_M);
            cudaEventRecord(evG[lyr][c], s1);

            cudaStreamWaitEvent(0, evG[lyr][c], 0);
            gru_scan<<<128, 256>>>(h0l, whh, bh, so, hn,
                                   c * CHUNK_T, (c + 1) * CHUNK_T, lyr);
            cudaEventRecord(evS[lyr][c], 0);
        }
    }
}

// round 10
// speedup vs baseline: 1.2122x; 1.2122x over previous
#include <cuda_runtime.h>

#define T_STEPS  2048
#define B_SZ     64
#define H_SZ     256
#define G3       768
#define M_TOT    (T_STEPS * B_SZ)
#define NCHUNK   4
#define CHUNK_T  (T_STEPS / NCHUNK)
#define CHUNK_M  (CHUNK_T * B_SZ)

typedef unsigned long long u64;

__device__ float g_gx[(size_t)M_TOT * G3];
__device__ float g_seq[(size_t)M_TOT * H_SZ];
struct PaddedCtr { unsigned int v; unsigned int pad[31]; };
__device__ PaddedCtr g_bar[3][4];

__global__ void reset_kernel() {
    int i = threadIdx.x;
    if (i < 12) g_bar[i / 4][i % 4].v = 0u;
}

__device__ __forceinline__ void ffma2(u64 &d, u64 a, u64 b) {
    asm("fma.rn.f32x2 %0, %1, %2, %0;" : "+l"(d) : "l"(a), "l"(b));
}
__device__ __forceinline__ u64 pack2(float lo, float hi) {
    u64 r; asm("mov.b64 %0, {%1, %2};" : "=l"(r) : "f"(lo), "f"(hi)); return r;
}
__device__ __forceinline__ float2 unpack2(u64 v) {
    float2 r; asm("mov.b64 {%0, %1}, %2;" : "=f"(r.x), "=f"(r.y) : "l"(v)); return r;
}
__device__ __forceinline__ float fsigmoid(float x) {
    float e; asm("ex2.approx.f32 %0, %1;" : "=f"(e) : "f"(-1.4426950408889634f * x));
    float r; asm("rcp.approx.f32 %0, %1;" : "=f"(r) : "f"(1.0f + e));
    return r;
}
__device__ __forceinline__ float ftanh(float x) {
    float y; asm("tanh.approx.f32 %0, %1;" : "=f"(y) : "f"(x)); return y;
}

// ---------------- Phase A: gx GEMM (chunked) ---------------------------------
__global__ __launch_bounds__(256) void gemm_gx(
    const float* __restrict__ A, const float* __restrict__ W,
    const float* __restrict__ bias, int m_base)
{
    __shared__ __align__(16) float As[32 * 132];
    __shared__ __align__(16) float Bs[32 * 64];
    const int tid = threadIdx.x, tx = tid & 15, ty = tid >> 4;
    const int m0 = m_base + blockIdx.x * 128, n0 = blockIdx.y * 64;

    float acc[8][4];
#pragma unroll
    for (int i = 0; i < 8; i++)
#pragma unroll
        for (int j = 0; j < 4; j++) acc[i][j] = 0.0f;

    for (int k0 = 0; k0 < 256; k0 += 32) {
#pragma unroll
        for (int i = 0; i < 4; i++) {
            int f = tid + 256 * i, r = f >> 3, c4 = f & 7;
            float4 v = *(const float4*)(A + (size_t)(m0 + r) * 256 + k0 + c4 * 4);
            As[(c4 * 4 + 0) * 132 + r] = v.x;
            As[(c4 * 4 + 1) * 132 + r] = v.y;
            As[(c4 * 4 + 2) * 132 + r] = v.z;
            As[(c4 * 4 + 3) * 132 + r] = v.w;
        }
#pragma unroll
        for (int i = 0; i < 2; i++) {
            int f = tid + 256 * i, r = f >> 3, c4 = f & 7;
            float4 v = *(const float4*)(W + (size_t)(n0 + r) * 256 + k0 + c4 * 4);
            Bs[(c4 * 4 + 0) * 64 + r] = v.x;
            Bs[(c4 * 4 + 1) * 64 + r] = v.y;
            Bs[(c4 * 4 + 2) * 64 + r] = v.z;
            Bs[(c4 * 4 + 3) * 64 + r] = v.w;
        }
        __syncthreads();
#pragma unroll
        for (int k = 0; k < 32; k++) {
            float a[8], b[4];
            *(float4*)&a[0] = *(const float4*)&As[k * 132 + ty * 8];
            *(float4*)&a[4] = *(const float4*)&As[k * 132 + ty * 8 + 4];
            *(float4*)&b[0] = *(const float4*)&Bs[k * 64 + tx * 4];
#pragma unroll
            for (int i = 0; i < 8; i++)
#pragma unroll
                for (int j = 0; j < 4; j++)
                    acc[i][j] = fmaf(a[i], b[j], acc[i][j]);
        }
        __syncthreads();
    }
    float4 bv = *(const float4*)(bias + n0 + tx * 4);
#pragma unroll
    for (int i = 0; i < 8; i++) {
        float4 o;
        o.x = acc[i][0] + bv.x; o.y = acc[i][1] + bv.y;
        o.z = acc[i][2] + bv.z; o.w = acc[i][3] + bv.w;
        *(float4*)(g_gx + (size_t)(m0 + ty * 8 + i) * G3 + n0 + tx * 4) = o;
    }
}

// ---------------- Phase B: scan. 64 CTAs = 16 ug x 4 bg ----------------------
// CTA: 16 units x 16 batches. Warp w: units u0 = ug*16 + 2w. Lanes: ks=l&15
// (k-slice), bh=l>>4 (batch half -> 8 local batches b0l = bh*8).
__global__ __launch_bounds__(256, 1) void gru_scan(
    const float* __restrict__ h0l, const float* __restrict__ Whh,
    const float* __restrict__ bhh, float* __restrict__ seqout,
    float* __restrict__ hn_out, int t0, int t1, int layer)
{
    __shared__ __align__(16) float hs[16][256];

    const int tid = threadIdx.x, w = tid >> 5, l = tid & 31;
    const int ks = l & 15, bh = l >> 4;
    const int bg = blockIdx.x & 3, ug = blockIdx.x >> 2;
    const int u0 = ug * 16 + w * 2;
    const int bgrp0 = bg * 16, b0l = bh * 8;

    int rows[6];
    rows[0] = u0;       rows[1] = u0 + 1;
    rows[2] = 256 + u0; rows[3] = 257 + u0;
    rows[4] = 512 + u0; rows[5] = 513 + u0;

    u64 wk[6][8];
#pragma unroll
    for (int r = 0; r < 6; r++)
#pragma unroll
        for (int kk = 0; kk < 4; kk++) {
            float4 v = *(const float4*)(Whh + (size_t)rows[r] * 256 + kk * 64 + ks * 4);
            wk[r][kk * 2 + 0] = pack2(v.x, v.y);
            wk[r][kk * 2 + 1] = pack2(v.z, v.w);
        }
    float bh6[6];
#pragma unroll
    for (int r = 0; r < 6; r++) bh6[r] = bhh[rows[r]];

    unsigned int* ctr = &g_bar[layer][bg].v;
    const int  j       = ks;
    const bool is_comb = (ks < 8);
    const int  bl      = b0l + j;            // local batch (combine lanes)
    const int  gb      = bgrp0 + bl;

    u64 gxv0 = 0, gxv1 = 0, gxv2 = 0;
    if (is_comb) {
        const float* gp = g_gx + ((size_t)t0 * B_SZ + gb) * G3;
        gxv0 = *(const u64*)(gp + u0);
        gxv1 = *(const u64*)(gp + 256 + u0);
        gxv2 = *(const u64*)(gp + 512 + u0);
    }

    for (int t = t0; t < t1; t++) {
        if (t > 0) {
            const unsigned int target = (unsigned int)t * 16u;
            unsigned int v;
            do {
                asm volatile("ld.acquire.gpu.global.u32 %0, [%1];"
                             : "=r"(v) : "l"(ctr) : "memory");
            } while (v < target);
        }

        // stage 16 batch rows (contiguous 16KB) into SMEM
        {
            const float* hsrc = (t == 0) ? h0l
                              : (seqout + (size_t)(t - 1) * (B_SZ * H_SZ));
            const float4* src = (const float4*)(hsrc + (size_t)bgrp0 * 256);
            float4* dst = (float4*)&hs[0][0];
#pragma unroll
            for (int i = 0; i < 4; i++)
                dst[tid + 256 * i] = __ldcg(src + tid + 256 * i);
        }
        __syncthreads();

        float hold0 = 0.0f, hold1 = 0.0f;
        if (is_comb) { hold0 = hs[bl][u0]; hold1 = hs[bl][u0 + 1]; }

#pragma unroll
        for (int bp = 0; bp < 4; bp++) {
            const int lA = b0l + 2 * bp, lB = lA + 1;
            u64 acc[6][2];
#pragma unroll
            for (int r = 0; r < 6; r++) { acc[r][0] = 0ULL; acc[r][1] = 0ULL; }
#pragma unroll
            for (int kk = 0; kk < 4; kk++) {
                ulonglong2 hA = *(const ulonglong2*)&hs[lA][kk * 64 + ks * 4];
                ulonglong2 hB = *(const ulonglong2*)&hs[lB][kk * 64 + ks * 4];
#pragma unroll
                for (int r = 0; r < 6; r++) {
                    ffma2(acc[r][0], wk[r][kk * 2 + 0], hA.x);
                    ffma2(acc[r][0], wk[r][kk * 2 + 1], hA.y);
                    ffma2(acc[r][1], wk[r][kk * 2 + 0], hB.x);
                    ffma2(acc[r][1], wk[r][kk * 2 + 1], hB.y);
                }
            }
            float sA[6], sB[6];
#pragma unroll
            for (int r = 0; r < 6; r++) {
                float2 a = unpack2(acc[r][0]); sA[r] = a.x + a.y;
                float2 b = unpack2(acc[r][1]); sB[r] = b.x + b.y;
            }
#pragma unroll
            for (int off = 1; off < 16; off <<= 1) {
#pragma unroll
                for (int r = 0; r < 6; r++) {
                    sA[r] += __shfl_xor_sync(0xFFFFFFFFu, sA[r], off);
                    sB[r] += __shfl_xor_sync(0xFFFFFFFFu, sB[r], off);
                }
            }
            if (is_comb && (j >> 1) == bp) {
                float s0, s1, s2, s3, s4, s5;
                if (j & 1) { s0=sB[0]; s1=sB[1]; s2=sB[2]; s3=sB[3]; s4=sB[4]; s5=sB[5]; }
                else       { s0=sA[0]; s1=sA[1]; s2=sA[2]; s3=sA[3]; s4=sA[4]; s5=sA[5]; }
                float2 gxr = unpack2(gxv0), gxz = unpack2(gxv1), gxn = unpack2(gxv2);

                float r0 = fsigmoid(gxr.x + s0 + bh6[0]);
                float z0 = fsigmoid(gxz.x + s2 + bh6[2]);
                float n0 = ftanh(gxn.x + r0 * (s4 + bh6[4]));
                float out0 = (1.0f - z0) * n0 + z0 * hold0;

                float r1 = fsigmoid(gxr.y + s1 + bh6[1]);
                float z1 = fsigmoid(gxz.y + s3 + bh6[3]);
                float n1 = ftanh(gxn.y + r1 * (s5 + bh6[5]));
                float out1 = (1.0f - z1) * n1 + z1 * hold1;

                u64 o = pack2(out0, out1);
                *(u64*)&seqout[((size_t)t * B_SZ + gb) * H_SZ + u0] = o;
                if (t == T_STEPS - 1)
                    *(u64*)&hn_out[gb * 256 + u0] = o;
            }
        }

        if (is_comb && (t + 1) < t1) {
            const float* gp = g_gx + ((size_t)(t + 1) * B_SZ + gb) * G3;
            gxv0 = *(const u64*)(gp + u0);
            gxv1 = *(const u64*)(gp + 256 + u0);
            gxv2 = *(const u64*)(gp + 512 + u0);
        }

        __syncthreads();
        if (tid == 0)
            asm volatile("red.release.gpu.global.add.u32 [%0], 1;"
                         :: "l"(ctr) : "memory");
    }
}

// ---------------- launch: layer-overlapped DAG -------------------------------
extern "C" void kernel_launch(void* const* d_in, const int* in_sizes, int n_in,
                              void* d_out, int out_size)
{
    const float* x   = (const float*)d_in[0];
    const float* h0  = (const float*)d_in[1];
    const float* Wih = (const float*)d_in[2];
    const float* Whh = (const float*)d_in[3];
    const float* bih = (const float*)d_in[4];
    const float* bhh = (const float*)d_in[5];

    float* out     = (float*)d_out;
    float* hn_base = out + (size_t)T_STEPS * B_SZ * H_SZ;

    void* gseq_ptr = nullptr;
    cudaGetSymbolAddress(&gseq_ptr, g_seq);
    float* gseq = (float*)gseq_ptr;

    static cudaStream_t s1 = nullptr;   // gemm (low priority)
    static cudaStream_t s2 = nullptr;   // layer-1 scan
    static cudaEvent_t evFork;
    static cudaEvent_t evG[3][NCHUNK];
    static cudaEvent_t evS[3][NCHUNK];
    if (!s1) {
        int loPri = 0, hiPri = 0;
        cudaDeviceGetStreamPriorityRange(&loPri, &hiPri);
        cudaStreamCreateWithPriority(&s1, cudaStreamNonBlocking, loPri);
        cudaStreamCreateWithFlags(&s2, cudaStreamNonBlocking);
        cudaEventCreateWithFlags(&evFork, cudaEventDisableTiming);
        for (int l = 0; l < 3; l++)
            for (int c = 0; c < NCHUNK; c++) {
                cudaEventCreateWithFlags(&evG[l][c], cudaEventDisableTiming);
                cudaEventCreateWithFlags(&evS[l][c], cudaEventDisableTiming);
            }
    }

    const size_t WSTRIDE = (size_t)G3 * 256;
    const size_t HSTRIDE = (size_t)B_SZ * H_SZ;
    const dim3 ggrid(CHUNK_M / 128, G3 / 64);

    reset_kernel<<<1, 32>>>();
    cudaEventRecord(evFork, 0);
    cudaStreamWaitEvent(s1, evFork, 0);
    cudaStreamWaitEvent(s2, evFork, 0);

    const float* layerA[3]   = { x, gseq, gseq };
    float*       layerOut[3] = { gseq, gseq, out };

    for (int lyr = 0; lyr < 3; lyr++) {
        const float* A   = layerA[lyr];
        float*       so  = layerOut[lyr];
        const float* wih = Wih + lyr * WSTRIDE;
        const float* whh = Whh + lyr * WSTRIDE;
        const float* bi  = bih + lyr * G3;
        const float* bh  = bhh + lyr * G3;
        const float* h0l = h0 + lyr * HSTRIDE;
        float*       hn  = hn_base + lyr * HSTRIDE;
        cudaStream_t sc  = (lyr == 1) ? s2 : (cudaStream_t)0;

        for (int c = 0; c < NCHUNK; c++) {
            if (lyr > 0)
                cudaStreamWaitEvent(s1, evS[lyr - 1][c], 0);
            gemm_gx<<<ggrid, 256, 0, s1>>>(A, wih, bi, c * CHUNK_M);
            cudaEventRecord(evG[lyr][c], s1);

            cudaStreamWaitEvent(sc, evG[lyr][c], 0);
            gru_scan<<<64, 256, 0, sc>>>(h0l, whh, bh, so, hn,
                                         c * CHUNK_T, (c + 1) * CHUNK_T, lyr);
            cudaEventRecord(evS[lyr][c], sc);
        }
    }
}